// round 4
// baseline (speedup 1.0000x reference)
#include <cuda_runtime.h>
#include <math.h>

// ---------------------------------------------------------------------------
// SmoothAP (quick_forward, sigmoid rank approx, 1-mAP), B x B scores/target.
// Single fused kernel: per-row AP -> device partials -> last block reduces.
//
//   ap[b] = (1/npos_b) * sum_{i : target[b,i]=1} (P_i + 0.5) / (A_i + 0.5)
//   A_i = sum_j sigmoid((s_j - s_i)/tau)           (diag 0.5 folded into +0.5)
//   P_i = sum_j sigmoid((s_j - s_i)/tau) * tg_j    (row-i target == row-b
//                                                   target when same class)
//   out = 1 - (1/B) * sum_b ap[b]
// ---------------------------------------------------------------------------

#define INV_TAU 100.0f   // 1 / 0.01
#define MAX_B   2048

__device__ float        g_partial[MAX_B];
__device__ unsigned int g_count = 0;     // ticket counter; re-armed each run

__global__ void sap_fused_kernel(const float* __restrict__ scores,
                                 const float* __restrict__ target,
                                 float* __restrict__ out, int B) {
    extern __shared__ float sh[];
    float* ss   = sh;            // scores row [B]
    float* st   = sh + B;        // target row [B]
    float* wred = sh + 2 * B;    // per-warp partials [nwarps]
    __shared__ bool isLast;

    const int b      = blockIdx.x;
    const int tid    = threadIdx.x;
    const int lane   = tid & 31;
    const int warp   = tid >> 5;
    const int nwarps = blockDim.x >> 5;

    const float* srow = scores + (size_t)b * B;
    const float* trow = target + (size_t)b * B;
    for (int j = tid; j < B; j += blockDim.x) {
        ss[j] = srow[j];
        st[j] = trow[j];
    }
    __syncthreads();

    // ---- per-row AP numerator: sum over positive i of (P+0.5)/(A+0.5) ----
    float sum_r = 0.0f;
    for (int i = warp; i < B; i += nwarps) {
        if (st[i] == 0.0f) continue;         // uniform across warp
        const float si = ss[i];
        float A = 0.0f, P = 0.0f;
        for (int j = lane; j < B; j += 32) {
            // sigmoid((s_j - s_i)/tau) = 1 / (1 + exp((s_i - s_j)/tau))
            float e  = __expf((si - ss[j]) * INV_TAU);
            float sg = __fdividef(1.0f, 1.0f + e);
            A += sg;
            P = fmaf(sg, st[j], P);
        }
#pragma unroll
        for (int o = 16; o; o >>= 1) {
            A += __shfl_xor_sync(0xffffffffu, A, o);
            P += __shfl_xor_sync(0xffffffffu, P, o);
        }
        sum_r += (P + 0.5f) / (A + 0.5f);
    }
    if (lane == 0) wred[warp] = sum_r;
    __syncthreads();

    // ---- block reduce + publish partial, grab ticket ----
    if (warp == 0) {
        float np = 0.0f;                      // npos_b = sum_j target[b,j]
        for (int j = lane; j < B; j += 32) np += st[j];
#pragma unroll
        for (int o = 16; o; o >>= 1) np += __shfl_xor_sync(0xffffffffu, np, o);

        float bs = (lane < nwarps) ? wred[lane] : 0.0f;
#pragma unroll
        for (int o = 16; o; o >>= 1) bs += __shfl_xor_sync(0xffffffffu, bs, o);

        if (lane == 0) {
            g_partial[b] = bs / np;
            __threadfence();
            unsigned int old = atomicAdd(&g_count, 1u);
            isLast = (old == (unsigned int)gridDim.x - 1u);
        }
    }
    __syncthreads();

    // ---- last block: reduce all partials, write output, re-arm counter ----
    if (isLast) {
        float v = 0.0f;
        for (int k = tid; k < gridDim.x; k += blockDim.x)
            v += __ldcg(&g_partial[k]);       // L2 read: skip (empty) L1
#pragma unroll
        for (int o = 16; o; o >>= 1) v += __shfl_xor_sync(0xffffffffu, v, o);
        if (lane == 0) wred[warp] = v;
        __syncthreads();
        if (warp == 0) {
            float t = (lane < nwarps) ? wred[lane] : 0.0f;
#pragma unroll
            for (int o = 16; o; o >>= 1) t += __shfl_xor_sync(0xffffffffu, t, o);
            if (lane == 0) {
                out[0] = 1.0f - t / (float)B;
                atomicExch(&g_count, 0u);     // deterministic re-arm for replay
            }
        }
    }
}

extern "C" void kernel_launch(void* const* d_in, const int* in_sizes, int n_in,
                              void* d_out, int out_size) {
    const float* scores = (const float*)d_in[0];
    const float* target = (const float*)d_in[1];
    float* out = (float*)d_out;

    int n = in_sizes[0];
    int B = 1;
    while ((long long)B * B < (long long)n) ++B;

    int threads = 512;
    if (threads > B) {
        threads = ((B + 31) / 32) * 32;
        if (threads < 32) threads = 32;
    }
    size_t smem = (size_t)2 * B * sizeof(float) + 32 * sizeof(float);

    sap_fused_kernel<<<B, threads, smem>>>(scores, target, out, B);
}

// round 5
// speedup vs baseline: 1.4386x; 1.4386x over previous
#include <cuda_runtime.h>
#include <math.h>

// ---------------------------------------------------------------------------
// SmoothAP (quick_forward, sigmoid rank approx, 1-mAP), B x B scores/target.
//
//   ap[b] = (1/npos_b) * sum_{i : target[b,i]=1} (P_i + 0.5) / (A_i + 0.5)
//   A_i = sum_j sigmoid((s_j - s_i)/tau)          (diag 0.5 folded into +0.5)
//   P_i = sum_j sigmoid((s_j - s_i)/tau) * tg_j   (row-i target == row-b
//                                                  target when same class)
//   out = 1 - (1/B) * sum_b ap[b]
//
// sigmoid((s_j-s_i)/tau) = 1 / (1 + exp2((s_i-s_j) * (1/tau)*log2e))
// Scores are pre-scaled by KSCALE at smem load, so the inner loop is
// FADD + EX2 + FADD + RCP + FADD + FFMA per element.
// ---------------------------------------------------------------------------

#define KSCALE 144.26950408889634f   // (1/0.01) * log2(e)

__device__ float        g_accum;     // zero-init at load; re-armed at end
__device__ unsigned int g_count = 0;

__device__ __forceinline__ float ex2a(float x) {
    float r; asm("ex2.approx.f32 %0, %1;" : "=f"(r) : "f"(x)); return r;
}
__device__ __forceinline__ float rcpa(float x) {
    float r; asm("rcp.approx.f32 %0, %1;" : "=f"(r) : "f"(x)); return r;
}

// ---------------- specialized kernel: B == 512, 512 threads ----------------
__global__ void __launch_bounds__(512)
sap512_kernel(const float* __restrict__ scores,
              const float* __restrict__ target,
              float* __restrict__ out, int grid) {
    constexpr int B  = 512;
    constexpr int NW = 16;                 // warps per block
    __shared__ __align__(16) float ssK[B]; // scores row, pre-scaled by KSCALE
    __shared__ __align__(16) float st[B];  // target row
    __shared__ float wsum[NW];
    __shared__ int   wcnt[NW];
    __shared__ short plist[B];
    __shared__ bool  isLast;

    const int b    = blockIdx.x;
    const int tid  = threadIdx.x;
    const int lane = tid & 31;
    const int warp = tid >> 5;

    const float* srow = scores + (size_t)b * B;
    const float* trow = target + (size_t)b * B;
    ssK[tid] = srow[tid] * KSCALE;
    st[tid]  = trow[tid];
    __syncthreads();

    // ---- deterministic ballot compaction of positive i's -------------------
    const int  j0 = warp * 32 + lane;
    const bool p  = (st[j0] != 0.0f);
    const unsigned m = __ballot_sync(0xffffffffu, p);
    if (lane == 0) wcnt[warp] = __popc(m);
    __syncthreads();
    int c      = (lane < NW) ? wcnt[lane] : 0;
    int total  = c;
    int before = (lane < warp) ? c : 0;
#pragma unroll
    for (int o = 16; o; o >>= 1) {
        total  += __shfl_xor_sync(0xffffffffu, total,  o);
        before += __shfl_xor_sync(0xffffffffu, before, o);
    }
    if (p) plist[before + __popc(m & ((1u << lane) - 1u))] = (short)j0;
    __syncthreads();

    // ---- main loop: one positive i per warp-iteration, balanced ------------
    const float4* ss4 = (const float4*)ssK;
    const float4* st4 = (const float4*)st;
    float sum_r = 0.0f;
    for (int k = warp; k < total; k += NW) {
        const int   i   = plist[k];
        const float siK = ssK[i];
        float A = 0.0f, P = 0.0f;
#pragma unroll
        for (int q = 0; q < B / 128; ++q) {
            // lane-coalesced: 32 lanes read one contiguous 512B chunk
            float4 s4 = ss4[q * 32 + lane];
            float4 t4 = st4[q * 32 + lane];
            float g0 = rcpa(1.0f + ex2a(siK - s4.x));
            float g1 = rcpa(1.0f + ex2a(siK - s4.y));
            float g2 = rcpa(1.0f + ex2a(siK - s4.z));
            float g3 = rcpa(1.0f + ex2a(siK - s4.w));
            A += (g0 + g1) + (g2 + g3);
            P = fmaf(g0, t4.x, fmaf(g1, t4.y, fmaf(g2, t4.z, fmaf(g3, t4.w, P))));
        }
#pragma unroll
        for (int o = 16; o; o >>= 1) {
            A += __shfl_xor_sync(0xffffffffu, A, o);
            P += __shfl_xor_sync(0xffffffffu, P, o);
        }
        sum_r += __fdividef(P + 0.5f, A + 0.5f);
    }
    if (lane == 0) wsum[warp] = sum_r;
    __syncthreads();

    // ---- block reduce, publish, ticket -------------------------------------
    if (warp == 0) {
        float bs = (lane < NW) ? wsum[lane] : 0.0f;
#pragma unroll
        for (int o = 16; o; o >>= 1) bs += __shfl_xor_sync(0xffffffffu, bs, o);
        if (lane == 0) {
            atomicAdd(&g_accum, __fdividef(bs, (float)total));
            __threadfence();
            unsigned old = atomicAdd(&g_count, 1u);
            isLast = (old == (unsigned)grid - 1u);
        }
    }
    __syncthreads();

    // ---- last block: finalize + re-arm for graph replay --------------------
    if (isLast && tid == 0) {
        float tot = atomicAdd(&g_accum, 0.0f);   // L2-coherent read
        out[0] = 1.0f - tot / (float)B;
        atomicExch(&g_accum, 0.0f);
        atomicExch(&g_count, 0u);
    }
}

// ---------------- generic fallback (any B): known-correct R4 structure ------
__global__ void sap_generic_kernel(const float* __restrict__ scores,
                                   const float* __restrict__ target,
                                   float* __restrict__ out, int B) {
    extern __shared__ float sh[];
    float* ss   = sh;
    float* st   = sh + B;
    float* wred = sh + 2 * B;
    __shared__ bool isLast;

    const int b      = blockIdx.x;
    const int tid    = threadIdx.x;
    const int lane   = tid & 31;
    const int warp   = tid >> 5;
    const int nwarps = blockDim.x >> 5;

    const float* srow = scores + (size_t)b * B;
    const float* trow = target + (size_t)b * B;
    for (int j = tid; j < B; j += blockDim.x) {
        ss[j] = srow[j] * KSCALE;
        st[j] = trow[j];
    }
    __syncthreads();

    float sum_r = 0.0f;
    for (int i = warp; i < B; i += nwarps) {
        if (st[i] == 0.0f) continue;
        const float siK = ss[i];
        float A = 0.0f, P = 0.0f;
        for (int j = lane; j < B; j += 32) {
            float g = rcpa(1.0f + ex2a(siK - ss[j]));
            A += g;
            P = fmaf(g, st[j], P);
        }
#pragma unroll
        for (int o = 16; o; o >>= 1) {
            A += __shfl_xor_sync(0xffffffffu, A, o);
            P += __shfl_xor_sync(0xffffffffu, P, o);
        }
        sum_r += __fdividef(P + 0.5f, A + 0.5f);
    }
    if (lane == 0) wred[warp] = sum_r;
    __syncthreads();

    if (warp == 0) {
        float np = 0.0f;
        for (int j = lane; j < B; j += 32) np += st[j];
#pragma unroll
        for (int o = 16; o; o >>= 1) np += __shfl_xor_sync(0xffffffffu, np, o);
        float bs = (lane < nwarps) ? wred[lane] : 0.0f;
#pragma unroll
        for (int o = 16; o; o >>= 1) bs += __shfl_xor_sync(0xffffffffu, bs, o);
        if (lane == 0) {
            atomicAdd(&g_accum, __fdividef(bs, np));
            __threadfence();
            unsigned old = atomicAdd(&g_count, 1u);
            isLast = (old == (unsigned)gridDim.x - 1u);
        }
    }
    __syncthreads();
    if (isLast && tid == 0) {
        float tot = atomicAdd(&g_accum, 0.0f);
        out[0] = 1.0f - tot / (float)B;
        atomicExch(&g_accum, 0.0f);
        atomicExch(&g_count, 0u);
    }
}

extern "C" void kernel_launch(void* const* d_in, const int* in_sizes, int n_in,
                              void* d_out, int out_size) {
    const float* scores = (const float*)d_in[0];
    const float* target = (const float*)d_in[1];
    float* out = (float*)d_out;

    int n = in_sizes[0];
    int B = 1;
    while ((long long)B * B < (long long)n) ++B;

    if (B == 512) {
        sap512_kernel<<<512, 512>>>(scores, target, out, 512);
    } else {
        int threads = 512;
        if (threads > B) {
            threads = ((B + 31) / 32) * 32;
            if (threads < 32) threads = 32;
        }
        size_t smem = (size_t)2 * B * sizeof(float) + 32 * sizeof(float);
        sap_generic_kernel<<<B, threads, smem>>>(scores, target, out, B);
    }
}

// round 6
// speedup vs baseline: 1.6442x; 1.1429x over previous
#include <cuda_runtime.h>
#include <math.h>

// ---------------------------------------------------------------------------
// SmoothAP (quick_forward, sigmoid rank approx, 1-mAP), B x B scores/target.
//
//   ap[b] = (1/npos_b) * sum_{i : target[b,i]=1} (P_i + 0.5) / (A_i + 0.5)
//   A_i = sum_j sigmoid((s_j - s_i)/tau)          (diag 0.5 folded into +0.5)
//   P_i = sum_j sigmoid((s_j - s_i)/tau) * tg_j
//   out = 1 - (1/B) * sum_b ap[b]
//
// sigmoid((s_j-s_i)/tau) = 1 / (1 + exp2((s_i-s_j) * (1/tau)*log2e)).
// Two kernels: per-row blocks write g_partial[b] (no atomics, no fences),
// then a 1-block kernel reduces.  Deterministic across graph replays.
// ---------------------------------------------------------------------------

#define KSCALE 144.26950408889634f   // (1/0.01) * log2(e)
#define MAX_B  2048

__device__ float        g_partial[MAX_B];
__device__ float        g_accum;          // generic fallback only
__device__ unsigned int g_count = 0;      // generic fallback only

__device__ __forceinline__ float ex2a(float x) {
    float r; asm("ex2.approx.f32 %0, %1;" : "=f"(r) : "f"(x)); return r;
}
__device__ __forceinline__ float rcpa(float x) {
    float r; asm("rcp.approx.f32 %0, %1;" : "=f"(r) : "f"(x)); return r;
}

// ---------------- main kernel: B == 512, 256 threads, 1 row/block -----------
__global__ void __launch_bounds__(256)
sap512_main(const float* __restrict__ scores,
            const float* __restrict__ target) {
    constexpr int B  = 512;
    constexpr int NW = 8;                  // warps per block
    __shared__ __align__(16) float ssK[B]; // scores row * KSCALE
    __shared__ __align__(16) float st[B];  // target row
    __shared__ float wsum[NW];
    __shared__ int   wcnt[2 * NW];
    __shared__ short plist[B];

    const int b    = blockIdx.x;
    const int tid  = threadIdx.x;
    const int lane = tid & 31;
    const int warp = tid >> 5;

    const float* srow = scores + (size_t)b * B;
    const float* trow = target + (size_t)b * B;
    ssK[tid]       = srow[tid]       * KSCALE;
    ssK[tid + 256] = srow[tid + 256] * KSCALE;
    st[tid]        = trow[tid];
    st[tid + 256]  = trow[tid + 256];
    __syncthreads();

    // ---- deterministic compaction of positive i's (16 groups of 32) -------
    const bool p0 = (st[tid]       != 0.0f);   // group  warp     : j = tid
    const bool p1 = (st[tid + 256] != 0.0f);   // group  8+warp   : j = tid+256
    const unsigned m0 = __ballot_sync(0xffffffffu, p0);
    const unsigned m1 = __ballot_sync(0xffffffffu, p1);
    if (lane == 0) { wcnt[warp] = __popc(m0); wcnt[NW + warp] = __popc(m1); }
    __syncthreads();

    // in-warp inclusive scan of the 16 group counts (every warp, redundantly)
    int c   = (lane < 2 * NW) ? wcnt[lane] : 0;
    int inc = c;
#pragma unroll
    for (int o = 1; o < 16; o <<= 1) {
        int t = __shfl_up_sync(0xffffffffu, inc, o);
        if (lane >= o) inc += t;
    }
    const int total   = __shfl_sync(0xffffffffu, inc, 15);
    const int exc     = inc - c;
    const int before0 = __shfl_sync(0xffffffffu, exc, warp);
    const int before1 = __shfl_sync(0xffffffffu, exc, NW + warp);
    const unsigned lt = (1u << lane) - 1u;
    if (p0) plist[before0 + __popc(m0 & lt)] = (short)tid;
    if (p1) plist[before1 + __popc(m1 & lt)] = (short)(tid + 256);
    __syncthreads();

    // ---- main loop: one positive i per warp, balanced ----------------------
    const float4* ss4 = (const float4*)ssK;
    const float4* st4 = (const float4*)st;
    float sum_r = 0.0f;
    for (int k = warp; k < total; k += NW) {
        const int   i   = plist[k];
        const float siK = ssK[i];
        float A = 0.0f, P = 0.0f;
#pragma unroll
        for (int q = 0; q < B / 128; ++q) {
            float4 s4 = ss4[q * 32 + lane];
            float4 t4 = st4[q * 32 + lane];
            float g0 = rcpa(1.0f + ex2a(siK - s4.x));
            float g1 = rcpa(1.0f + ex2a(siK - s4.y));
            float g2 = rcpa(1.0f + ex2a(siK - s4.z));
            float g3 = rcpa(1.0f + ex2a(siK - s4.w));
            A += (g0 + g1) + (g2 + g3);
            P = fmaf(g0, t4.x, fmaf(g1, t4.y, fmaf(g2, t4.z, fmaf(g3, t4.w, P))));
        }
#pragma unroll
        for (int o = 16; o; o >>= 1) {
            A += __shfl_xor_sync(0xffffffffu, A, o);
            P += __shfl_xor_sync(0xffffffffu, P, o);
        }
        sum_r += __fdividef(P + 0.5f, A + 0.5f);
    }
    if (lane == 0) wsum[warp] = sum_r;
    __syncthreads();

    if (warp == 0) {
        float bs = (lane < NW) ? wsum[lane] : 0.0f;
#pragma unroll
        for (int o = 4; o; o >>= 1) bs += __shfl_xor_sync(0xffffffffu, bs, o);
        if (lane == 0) g_partial[b] = __fdividef(bs, (float)total);
    }
}

// ---------------- reduce kernel: 1 block, 512 partials ----------------------
__global__ void __launch_bounds__(512)
sap512_reduce(float* __restrict__ out) {
    __shared__ float red[16];
    const int tid  = threadIdx.x;
    const int lane = tid & 31;
    const int warp = tid >> 5;
    float v = g_partial[tid];
#pragma unroll
    for (int o = 16; o; o >>= 1) v += __shfl_xor_sync(0xffffffffu, v, o);
    if (lane == 0) red[warp] = v;
    __syncthreads();
    if (warp == 0) {
        float t = (lane < 16) ? red[lane] : 0.0f;
#pragma unroll
        for (int o = 8; o; o >>= 1) t += __shfl_xor_sync(0xffffffffu, t, o);
        if (lane == 0) out[0] = 1.0f - t * (1.0f / 512.0f);
    }
}

// ---------------- generic fallback (any B) ----------------------------------
__global__ void sap_generic_kernel(const float* __restrict__ scores,
                                   const float* __restrict__ target,
                                   float* __restrict__ out, int B) {
    extern __shared__ float sh[];
    float* ss   = sh;
    float* st   = sh + B;
    float* wred = sh + 2 * B;
    __shared__ bool isLast;

    const int b      = blockIdx.x;
    const int tid    = threadIdx.x;
    const int lane   = tid & 31;
    const int warp   = tid >> 5;
    const int nwarps = blockDim.x >> 5;

    const float* srow = scores + (size_t)b * B;
    const float* trow = target + (size_t)b * B;
    for (int j = tid; j < B; j += blockDim.x) {
        ss[j] = srow[j] * KSCALE;
        st[j] = trow[j];
    }
    __syncthreads();

    float sum_r = 0.0f;
    for (int i = warp; i < B; i += nwarps) {
        if (st[i] == 0.0f) continue;
        const float siK = ss[i];
        float A = 0.0f, P = 0.0f;
        for (int j = lane; j < B; j += 32) {
            float g = rcpa(1.0f + ex2a(siK - ss[j]));
            A += g;
            P = fmaf(g, st[j], P);
        }
#pragma unroll
        for (int o = 16; o; o >>= 1) {
            A += __shfl_xor_sync(0xffffffffu, A, o);
            P += __shfl_xor_sync(0xffffffffu, P, o);
        }
        sum_r += __fdividef(P + 0.5f, A + 0.5f);
    }
    if (lane == 0) wred[warp] = sum_r;
    __syncthreads();

    if (warp == 0) {
        float np = 0.0f;
        for (int j = lane; j < B; j += 32) np += st[j];
#pragma unroll
        for (int o = 16; o; o >>= 1) np += __shfl_xor_sync(0xffffffffu, np, o);
        float bs = (lane < nwarps) ? wred[lane] : 0.0f;
#pragma unroll
        for (int o = 16; o; o >>= 1) bs += __shfl_xor_sync(0xffffffffu, bs, o);
        if (lane == 0) {
            atomicAdd(&g_accum, __fdividef(bs, np));
            __threadfence();
            unsigned old = atomicAdd(&g_count, 1u);
            isLast = (old == (unsigned)gridDim.x - 1u);
        }
    }
    __syncthreads();
    if (isLast && tid == 0) {
        float tot = atomicAdd(&g_accum, 0.0f);
        out[0] = 1.0f - tot / (float)B;
        atomicExch(&g_accum, 0.0f);
        atomicExch(&g_count, 0u);
    }
}

extern "C" void kernel_launch(void* const* d_in, const int* in_sizes, int n_in,
                              void* d_out, int out_size) {
    const float* scores = (const float*)d_in[0];
    const float* target = (const float*)d_in[1];
    float* out = (float*)d_out;

    int n = in_sizes[0];
    int B = 1;
    while ((long long)B * B < (long long)n) ++B;

    if (B == 512) {
        sap512_main<<<512, 256>>>(scores, target);
        sap512_reduce<<<1, 512>>>(out);
    } else {
        int threads = 512;
        if (threads > B) {
            threads = ((B + 31) / 32) * 32;
            if (threads < 32) threads = 32;
        }
        size_t smem = (size_t)2 * B * sizeof(float) + 32 * sizeof(float);
        sap_generic_kernel<<<B, threads, smem>>>(scores, target, out, B);
    }
}

// round 7
// speedup vs baseline: 2.0354x; 1.2379x over previous
#include <cuda_runtime.h>
#include <math.h>

// ---------------------------------------------------------------------------
// SmoothAP (quick_forward, sigmoid rank approx, 1-mAP), B x B scores/target.
//
//   ap[b] = (1/npos_b) * sum_{i : target[b,i]=1} sim_pos_i / sim_all_i
// Using sigmoid(y) = 0.5*(1 + tanh(y/2)), with scores pre-scaled by 1/(2*tau):
//   T_i  = sum_j tanh(50*(s_j - s_i))          (all j; diag tanh(0)=0)
//   Tp_i = sum_j tanh(50*(s_j - s_i)) * tg_j
//   ratio_i = (Tp_i + np + 1) / (T_i + B + 1)  (np = #positives incl. diag)
//   out = 1 - (1/B) * mean_b ( sum_i ratio_i / np )
//
// Single fused kernel: per-row blocks write g_partial[b] (plain STG),
// last block (ticket) reduces.  Deterministic across graph replays.
// ---------------------------------------------------------------------------

#define KSCALE 50.0f        // 1/(2*tau) = 1/(2*0.01)
#define MAX_B  2048

__device__ float        g_partial[MAX_B];
__device__ float        g_accum;          // generic fallback only
__device__ unsigned int g_count = 0;      // ticket counter; re-armed each run

__device__ __forceinline__ float tanha(float x) {
    float r; asm("tanh.approx.f32 %0, %1;" : "=f"(r) : "f"(x)); return r;
}
__device__ __forceinline__ float ex2a(float x) {
    float r; asm("ex2.approx.f32 %0, %1;" : "=f"(r) : "f"(x)); return r;
}
__device__ __forceinline__ float rcpa(float x) {
    float r; asm("rcp.approx.f32 %0, %1;" : "=f"(r) : "f"(x)); return r;
}

// ---------------- fused kernel: B == 512, 256 threads, 1 row/block ----------
__global__ void __launch_bounds__(256)
sap512_fused(const float* __restrict__ scores,
             const float* __restrict__ target,
             float* __restrict__ out) {
    constexpr int B  = 512;
    constexpr int NW = 8;                  // warps per block
    __shared__ __align__(16) float ssK[B]; // scores row * KSCALE
    __shared__ __align__(16) float st[B];  // target row
    __shared__ float wsum[NW];
    __shared__ int   wcnt[2 * NW];
    __shared__ short plist[B];
    __shared__ bool  isLast;

    const int b    = blockIdx.x;
    const int tid  = threadIdx.x;
    const int lane = tid & 31;
    const int warp = tid >> 5;

    const float* srow = scores + (size_t)b * B;
    const float* trow = target + (size_t)b * B;
    ssK[tid]       = srow[tid]       * KSCALE;
    ssK[tid + 256] = srow[tid + 256] * KSCALE;
    st[tid]        = trow[tid];
    st[tid + 256]  = trow[tid + 256];
    __syncthreads();

    // ---- deterministic compaction of positive i's (16 groups of 32) -------
    const bool p0 = (st[tid]       != 0.0f);
    const bool p1 = (st[tid + 256] != 0.0f);
    const unsigned m0 = __ballot_sync(0xffffffffu, p0);
    const unsigned m1 = __ballot_sync(0xffffffffu, p1);
    if (lane == 0) { wcnt[warp] = __popc(m0); wcnt[NW + warp] = __popc(m1); }
    __syncthreads();

    int c   = (lane < 2 * NW) ? wcnt[lane] : 0;
    int inc = c;
#pragma unroll
    for (int o = 1; o < 16; o <<= 1) {
        int t = __shfl_up_sync(0xffffffffu, inc, o);
        if (lane >= o) inc += t;
    }
    const int total   = __shfl_sync(0xffffffffu, inc, 15);  // np (incl. diag)
    const int exc     = inc - c;
    const int before0 = __shfl_sync(0xffffffffu, exc, warp);
    const int before1 = __shfl_sync(0xffffffffu, exc, NW + warp);
    const unsigned lt = (1u << lane) - 1u;
    if (p0) plist[before0 + __popc(m0 & lt)] = (short)tid;
    if (p1) plist[before1 + __popc(m1 & lt)] = (short)(tid + 256);
    __syncthreads();

    // ---- main loop: one positive i per warp, balanced ----------------------
    const float4* ss4 = (const float4*)ssK;
    const float4* st4 = (const float4*)st;
    const float numc = (float)(total + 1);        // np + 1
    float sum_r = 0.0f;
    for (int k = warp; k < total; k += NW) {
        const int   i   = plist[k];
        const float siK = ssK[i];
        float T = 0.0f, Tp = 0.0f;
#pragma unroll
        for (int q = 0; q < B / 128; ++q) {
            float4 s4 = ss4[q * 32 + lane];
            float4 t4 = st4[q * 32 + lane];
            float t0 = tanha(s4.x - siK);
            float t1 = tanha(s4.y - siK);
            float t2 = tanha(s4.z - siK);
            float t3 = tanha(s4.w - siK);
            T += (t0 + t1) + (t2 + t3);
            Tp = fmaf(t0, t4.x, fmaf(t1, t4.y, fmaf(t2, t4.z, fmaf(t3, t4.w, Tp))));
        }
#pragma unroll
        for (int o = 16; o; o >>= 1) {
            T  += __shfl_xor_sync(0xffffffffu, T,  o);
            Tp += __shfl_xor_sync(0xffffffffu, Tp, o);
        }
        sum_r += __fdividef(Tp + numc, T + (float)(B + 1));
    }
    if (lane == 0) wsum[warp] = sum_r;
    __syncthreads();

    // ---- block reduce, publish partial, grab ticket ------------------------
    if (warp == 0) {
        float bs = (lane < NW) ? wsum[lane] : 0.0f;
#pragma unroll
        for (int o = 4; o; o >>= 1) bs += __shfl_xor_sync(0xffffffffu, bs, o);
        if (lane == 0) {
            g_partial[b] = __fdividef(bs, (float)total);
            __threadfence();
            unsigned old = atomicAdd(&g_count, 1u);
            isLast = (old == (unsigned)(gridDim.x - 1));
        }
    }
    __syncthreads();

    // ---- last block: reduce 512 partials, write output, re-arm -------------
    if (isLast) {
        float v = __ldcg(&g_partial[tid]) + __ldcg(&g_partial[tid + 256]);
#pragma unroll
        for (int o = 16; o; o >>= 1) v += __shfl_xor_sync(0xffffffffu, v, o);
        if (lane == 0) wsum[warp] = v;
        __syncthreads();
        if (warp == 0) {
            float t = (lane < NW) ? wsum[lane] : 0.0f;
#pragma unroll
            for (int o = 4; o; o >>= 1) t += __shfl_xor_sync(0xffffffffu, t, o);
            if (lane == 0) {
                out[0] = 1.0f - t * (1.0f / 512.0f);
                atomicExch(&g_count, 0u);     // re-arm for next graph replay
            }
        }
    }
}

// ---------------- generic fallback (any B) ----------------------------------
__global__ void sap_generic_kernel(const float* __restrict__ scores,
                                   const float* __restrict__ target,
                                   float* __restrict__ out, int B) {
    extern __shared__ float sh[];
    float* ss   = sh;
    float* st   = sh + B;
    float* wred = sh + 2 * B;
    __shared__ bool isLast;

    const int b      = blockIdx.x;
    const int tid    = threadIdx.x;
    const int lane   = tid & 31;
    const int warp   = tid >> 5;
    const int nwarps = blockDim.x >> 5;

    const float* srow = scores + (size_t)b * B;
    const float* trow = target + (size_t)b * B;
    for (int j = tid; j < B; j += blockDim.x) {
        ss[j] = srow[j] * 144.26950408889634f;   // (1/tau)*log2e
        st[j] = trow[j];
    }
    __syncthreads();

    float sum_r = 0.0f;
    for (int i = warp; i < B; i += nwarps) {
        if (st[i] == 0.0f) continue;
        const float siK = ss[i];
        float A = 0.0f, P = 0.0f;
        for (int j = lane; j < B; j += 32) {
            float g = rcpa(1.0f + ex2a(siK - ss[j]));
            A += g;
            P = fmaf(g, st[j], P);
        }
#pragma unroll
        for (int o = 16; o; o >>= 1) {
            A += __shfl_xor_sync(0xffffffffu, A, o);
            P += __shfl_xor_sync(0xffffffffu, P, o);
        }
        sum_r += __fdividef(P + 0.5f, A + 0.5f);
    }
    if (lane == 0) wred[warp] = sum_r;
    __syncthreads();

    if (warp == 0) {
        float np = 0.0f;
        for (int j = lane; j < B; j += 32) np += st[j];
#pragma unroll
        for (int o = 16; o; o >>= 1) np += __shfl_xor_sync(0xffffffffu, np, o);
        float bs = (lane < nwarps) ? wred[lane] : 0.0f;
#pragma unroll
        for (int o = 16; o; o >>= 1) bs += __shfl_xor_sync(0xffffffffu, bs, o);
        if (lane == 0) {
            atomicAdd(&g_accum, __fdividef(bs, np));
            __threadfence();
            unsigned old = atomicAdd(&g_count, 1u);
            isLast = (old == (unsigned)gridDim.x - 1u);
        }
    }
    __syncthreads();
    if (isLast && tid == 0) {
        float tot = atomicAdd(&g_accum, 0.0f);
        out[0] = 1.0f - tot / (float)B;
        atomicExch(&g_accum, 0.0f);
        atomicExch(&g_count, 0u);
    }
}

extern "C" void kernel_launch(void* const* d_in, const int* in_sizes, int n_in,
                              void* d_out, int out_size) {
    const float* scores = (const float*)d_in[0];
    const float* target = (const float*)d_in[1];
    float* out = (float*)d_out;

    int n = in_sizes[0];
    int B = 1;
    while ((long long)B * B < (long long)n) ++B;

    if (B == 512) {
        sap512_fused<<<512, 256>>>(scores, target, out);
    } else {
        int threads = 512;
        if (threads > B) {
            threads = ((B + 31) / 32) * 32;
            if (threads < 32) threads = 32;
        }
        size_t smem = (size_t)2 * B * sizeof(float) + 32 * sizeof(float);
        sap_generic_kernel<<<B, threads, smem>>>(scores, target, out, B);
    }
}